// round 16
// baseline (speedup 1.0000x reference)
#include <cuda_runtime.h>
#include <cuda_fp16.h>
#include <cuda.h>
#include <cstdint>

// LSTM cell: gates = [x|h] @ [Wx;Wh] + bx + bh, fused epilogue.
// B=16384, IN=H=512, K=1024, N=4H=2048.
// Round 16: TMA (cp.async.bulk.tensor.2d, sm_90 baseline) replaces the
// 16-per-thread cp.async bursts -- removes 256 issue-cyc/SMSP/iter of
// LDGSTS from the issue port (the measured bottleneck). SW128 swizzled
// stages, ldmatrix with per-lane XOR swizzle. Full barriers: expect_tx.
// prep (R13) + PDL (R15) + mainloop dataflow (R11) otherwise unchanged.

static constexpr int Bsz  = 16384;
static constexpr int INF  = 512;
static constexpr int Hd   = 512;
static constexpr int FH   = 2048;
static constexpr int Ktot = 1024;

#define BM 128
#define BN 128
#define BK 64
#define NSTAGE 3
#define NITER (Ktot / BK)              // 16
#define A_TILE_B 16384                 // 128 rows x 128B (SW128, no pad)
#define STG_B    32768                 // A + B
#define SMEM_BYTES (1024 + NSTAGE * STG_B)   // 99328
#define TX_BYTES 32768u

#define PREP_A_BLKS 2048
#define PREP_W_BLKS (32 * 64)
#define PREP_BLKS   (PREP_A_BLKS + PREP_W_BLKS)

__device__ __half g_A16[(size_t)Bsz * Ktot];   // 32 MB [b][k]  (x | h)
__device__ __half g_Bt16[(size_t)FH * Ktot];   // 4 MB  [n'][k] gate-interleaved(16)

// ---------------- device helpers ----------------
__device__ __forceinline__ uint32_t cvta_s(const void* p) {
    return (uint32_t)__cvta_generic_to_shared(p);
}
__device__ __forceinline__ void mbar_init(uint32_t a, uint32_t cnt) {
    asm volatile("mbarrier.init.shared.b64 [%0], %1;" :: "r"(a), "r"(cnt) : "memory");
}
__device__ __forceinline__ void mbar_arrive(uint32_t a) {
    asm volatile("mbarrier.arrive.shared.b64 _, [%0];" :: "r"(a) : "memory");
}
__device__ __forceinline__ void mbar_expect_tx(uint32_t a, uint32_t tx) {
    asm volatile("mbarrier.arrive.expect_tx.shared.b64 _, [%0], %1;"
                 :: "r"(a), "r"(tx) : "memory");
}
__device__ __forceinline__ void mbar_wait(uint32_t a, uint32_t ph) {
    uint32_t done = 0;
    while (!done) {
        asm volatile(
            "{\n\t.reg .pred p;\n\t"
            "mbarrier.try_wait.parity.acquire.cta.shared::cta.b64 p, [%1], %2, 0x989680;\n\t"
            "selp.b32 %0, 1, 0, p;\n\t}"
            : "=r"(done) : "r"(a), "r"(ph) : "memory");
    }
}
__device__ __forceinline__ void tma2d(uint32_t smem, const CUtensorMap* tm,
                                      int x, int y, uint32_t bar) {
    asm volatile(
        "cp.async.bulk.tensor.2d.shared::cta.global.tile.mbarrier::complete_tx::bytes "
        "[%0], [%1, {%2, %3}], [%4];"
        :: "r"(smem), "l"(tm), "r"(x), "r"(y), "r"(bar) : "memory");
}
__device__ __forceinline__ void ldm4(uint32_t* r, uint32_t a) {
    asm volatile("ldmatrix.sync.aligned.m8n8.x4.shared.b16 {%0,%1,%2,%3}, [%4];"
                 : "=r"(r[0]), "=r"(r[1]), "=r"(r[2]), "=r"(r[3]) : "r"(a));
}
__device__ __forceinline__ void mma16(float* d, const uint32_t* a, const uint32_t* b) {
    asm volatile(
        "mma.sync.aligned.m16n8k16.row.col.f32.f16.f16.f32 "
        "{%0,%1,%2,%3}, {%4,%5,%6,%7}, {%8,%9}, {%0,%1,%2,%3};"
        : "+f"(d[0]), "+f"(d[1]), "+f"(d[2]), "+f"(d[3])
        : "r"(a[0]), "r"(a[1]), "r"(a[2]), "r"(a[3]), "r"(b[0]), "r"(b[1]));
}
__device__ __forceinline__ float rcp_(float a) {
    float r; asm("rcp.approx.f32 %0, %1;" : "=f"(r) : "f"(a)); return r;
}
__device__ __forceinline__ float sigm_(float v) { return rcp_(1.0f + __expf(-v)); }
__device__ __forceinline__ float tanh_(float v) {
    return 2.0f * rcp_(1.0f + __expf(-2.0f * v)) - 1.0f;
}
__device__ __forceinline__ uint4 pack8h(const float4& a, const float4& b) {
    union { __half2 h2[4]; uint4 u; } u;
    u.h2[0] = __floats2half2_rn(a.x, a.y);
    u.h2[1] = __floats2half2_rn(a.z, a.w);
    u.h2[2] = __floats2half2_rn(b.x, b.y);
    u.h2[3] = __floats2half2_rn(b.z, b.w);
    return u.u;
}

// ---------------- merged prepass (R13 + PDL, validated) ----------------
__global__ void prep_all(const float* __restrict__ x, const float* __restrict__ h,
                         const float* __restrict__ Wx, const float* __restrict__ Wh)
{
    asm volatile("griddepcontrol.launch_dependents;");

    if (blockIdx.x < PREP_A_BLKS) {
        const size_t t = (size_t)blockIdx.x * 256 + threadIdx.x;
        const size_t NG = (size_t)Bsz * INF / 8;
        const size_t S  = NG / 2;
        const size_t g0 = t, g1 = t + S;
        float4 x0a = *reinterpret_cast<const float4*>(x + g0 * 8);
        float4 x0b = *reinterpret_cast<const float4*>(x + g0 * 8 + 4);
        float4 x1a = *reinterpret_cast<const float4*>(x + g1 * 8);
        float4 x1b = *reinterpret_cast<const float4*>(x + g1 * 8 + 4);
        float4 h0a = *reinterpret_cast<const float4*>(h + g0 * 8);
        float4 h0b = *reinterpret_cast<const float4*>(h + g0 * 8 + 4);
        float4 h1a = *reinterpret_cast<const float4*>(h + g1 * 8);
        float4 h1b = *reinterpret_cast<const float4*>(h + g1 * 8 + 4);
        {   size_t b = g0 >> 6, c8 = (g0 & 63) * 8;
            *reinterpret_cast<uint4*>(g_A16 + b * Ktot + c8) = pack8h(x0a, x0b);
            *reinterpret_cast<uint4*>(g_A16 + b * Ktot + 512 + c8) = pack8h(h0a, h0b);
        }
        {   size_t b = g1 >> 6, c8 = (g1 & 63) * 8;
            *reinterpret_cast<uint4*>(g_A16 + b * Ktot + c8) = pack8h(x1a, x1b);
            *reinterpret_cast<uint4*>(g_A16 + b * Ktot + 512 + c8) = pack8h(h1a, h1b);
        }
        return;
    }

    __shared__ float t[32][33];
    const int wb = blockIdx.x - PREP_A_BLKS;
    const int k0 = (wb & 31) * 32;
    const int n0 = (wb >> 5) * 32;
    const float* W = (k0 < INF) ? (Wx + (size_t)k0 * FH)
                                : (Wh + (size_t)(k0 - INF) * FH);
    const int tx = threadIdx.x & 31, ty = threadIdx.x >> 5;
    #pragma unroll
    for (int i = 0; i < 4; ++i) {
        int kk = ty + i * 8;
        t[kk][tx] = W[(size_t)kk * FH + n0 + tx];
    }
    __syncthreads();
    const int gate = n0 >> 9;
    const int j0   = n0 & 511;
    #pragma unroll
    for (int i = 0; i < 4; ++i) {
        int nn = ty + i * 8;
        int j  = j0 + nn;
        int np = ((j >> 4) << 6) + gate * 16 + (j & 15);
        g_Bt16[(size_t)np * Ktot + k0 + tx] = __float2half_rn(t[tx][nn]);
    }
}

// ---------------- main GEMM + LSTM epilogue (TMA producer) ----------------
__global__ __launch_bounds__(128, 2)
void lstm_mma(const __grid_constant__ CUtensorMap tmA,
              const __grid_constant__ CUtensorMap tmB,
              const float* __restrict__ c,
              const float* __restrict__ bx, const float* __restrict__ bh,
              float* __restrict__ out)
{
    extern __shared__ char smraw[];
    float* biasS = reinterpret_cast<float*>(smraw);
    char*  stg0  = smraw + 1024;

    const int tid  = threadIdx.x;
    const int lane = tid & 31;
    const int wid  = tid >> 5;
    const int wm   = wid >> 1;
    const int wn   = wid & 1;
    const int m0   = blockIdx.y * BM;
    const int n0   = blockIdx.x * BN;
    const int jb   = blockIdx.x * 32;

    const uint32_t sbase = cvta_s(smraw);
    const uint32_t FULLB = sbase + 512;
    const uint32_t EMPTB = sbase + 512 + 24;
    const uint32_t STAGE0 = sbase + 1024;

    if (tid == 0) {
        #pragma unroll
        for (int s = 0; s < NSTAGE; ++s) {
            mbar_init(FULLB + s * 8, 1);      // arrive from expect_tx only
            mbar_init(EMPTB + s * 8, 128);
        }
    }
    {   int g = tid >> 5, jj = tid & 31;
        int colg = g * 512 + jb + jj;
        biasS[tid] = bx[colg] + bh[colg];
    }
    __syncthreads();    // publishes mbarrier init + bias

    // PDL: prep output (g_A16 / g_Bt16) must be visible before TMA reads it
    asm volatile("griddepcontrol.wait;" ::: "memory");

    // prologue: issue TMA for stages 0 and 1 (one thread)
    if (tid == 0) {
        mbar_expect_tx(FULLB + 0, TX_BYTES);
        tma2d(STAGE0,            &tmA, 0,  m0, FULLB + 0);
        tma2d(STAGE0 + A_TILE_B, &tmB, 0,  n0, FULLB + 0);
        mbar_expect_tx(FULLB + 8, TX_BYTES);
        tma2d(STAGE0 + STG_B,            &tmA, BK, m0, FULLB + 8);
        tma2d(STAGE0 + STG_B + A_TILE_B, &tmB, BK, n0, FULLB + 8);
    }

    float acc[4][8][4];
    #pragma unroll
    for (int a = 0; a < 4; ++a)
        #pragma unroll
        for (int b = 0; b < 8; ++b)
            #pragma unroll
            for (int d = 0; d < 4; ++d) acc[a][b][d] = 0.0f;

    // ldmatrix geometry with SW128 swizzle:
    // stored byte = row*128 + (kbyte ^ ((row&7)<<4)); row&7 == gi here.
    const int grp = lane >> 3, gi = lane & 7;
    const uint32_t swm = (uint32_t)gi << 4;
    const uint32_t a_rowoff = (uint32_t)(wm * 64 + (grp & 1) * 8 + gi) * 128;
    const uint32_t b_rowoff = (uint32_t)(wn * 64 + (grp >> 1) * 8 + gi) * 128;
    const uint32_t akh = (uint32_t)((grp >> 1) * 16);   // A k-half byte
    const uint32_t bkh = (uint32_t)((grp & 1) * 16);    // B k-half byte
    uint32_t koffA[4], koffB[4];
    #pragma unroll
    for (int ks = 0; ks < 4; ++ks) {
        koffA[ks] = (akh + (uint32_t)ks * 32) ^ swm;
        koffB[ks] = (bkh + (uint32_t)ks * 32) ^ swm;
    }

    uint32_t afr[2][4][4], bfr[2][4][4];
    int fph0 = 0, fph1 = 0, fph2 = 0;
    int eph0 = 0, eph1 = 0, eph2 = 0;

    // prologue: wait stage 0, preload its ks=0 fragments
    mbar_wait(FULLB + 0, 0); fph0 = 1;
    {
        const uint32_t sA = STAGE0 + a_rowoff;
        const uint32_t sB = STAGE0 + A_TILE_B + b_rowoff;
        #pragma unroll
        for (int mf = 0; mf < 4; ++mf)
            ldm4(afr[0][mf], sA + mf * 2048 + koffA[0]);
        #pragma unroll
        for (int np = 0; np < 4; ++np)
            ldm4(bfr[0][np], sB + np * 2048 + koffB[0]);
    }

    for (int it = 0; it < NITER; ++it) {
        const int s = it % NSTAGE;

        // producer: refill stage (it+2)%3 once its consumers drained
        if (it + 2 < NITER && tid == 0) {
            const int s2 = (it + 2) % NSTAGE;
            if (it > 0) {
                int ph = (s2 == 0) ? eph0 : (s2 == 1) ? eph1 : eph2;
                mbar_wait(EMPTB + s2 * 8, ph);
                if (s2 == 0) eph0 ^= 1; else if (s2 == 1) eph1 ^= 1; else eph2 ^= 1;
            }
            const uint32_t dst = STAGE0 + s2 * STG_B;
            mbar_expect_tx(FULLB + s2 * 8, TX_BYTES);
            tma2d(dst,            &tmA, (it + 2) * BK, m0, FULLB + s2 * 8);
            tma2d(dst + A_TILE_B, &tmB, (it + 2) * BK, n0, FULLB + s2 * 8);
        }

        const uint32_t sA = STAGE0 + s * STG_B + a_rowoff;
        const uint32_t sB = STAGE0 + s * STG_B + A_TILE_B + b_rowoff;

        #pragma unroll
        for (int ks = 0; ks < 4; ++ks) {
            const int cur = ks & 1;
            const int nxt = cur ^ 1;
            if (ks < 3) {
                #pragma unroll
                for (int mf = 0; mf < 4; ++mf)
                    ldm4(afr[nxt][mf], sA + mf * 2048 + koffA[ks + 1]);
                #pragma unroll
                for (int np = 0; np < 4; ++np)
                    ldm4(bfr[nxt][np], sB + np * 2048 + koffB[ks + 1]);
                if (ks == 2)
                    mbar_arrive(EMPTB + s * 8);   // last smem read of stage s
            } else if (it + 1 < NITER) {
                const int s1 = (it + 1) % NSTAGE;
                int ph = (s1 == 0) ? fph0 : (s1 == 1) ? fph1 : fph2;
                mbar_wait(FULLB + s1 * 8, ph);
                if (s1 == 0) fph0 ^= 1; else if (s1 == 1) fph1 ^= 1; else fph2 ^= 1;
                const uint32_t nA = STAGE0 + s1 * STG_B + a_rowoff;
                const uint32_t nB = STAGE0 + s1 * STG_B + A_TILE_B + b_rowoff;
                #pragma unroll
                for (int mf = 0; mf < 4; ++mf)
                    ldm4(afr[nxt][mf], nA + mf * 2048 + koffA[0]);
                #pragma unroll
                for (int np = 0; np < 4; ++np)
                    ldm4(bfr[nxt][np], nB + np * 2048 + koffB[0]);
            }
            #pragma unroll
            for (int mf = 0; mf < 4; ++mf)
                #pragma unroll
                for (int np = 0; np < 4; ++np) {
                    mma16(acc[mf][np * 2 + 0], afr[cur][mf], &bfr[cur][np][0]);
                    mma16(acc[mf][np * 2 + 1], afr[cur][mf], &bfr[cur][np][2]);
                }
        }
    }

    // ---- fused LSTM epilogue (thread-local: all 4 gates per j) ----
    const size_t HC = (size_t)Bsz * Hd;
    #pragma unroll
    for (int mf = 0; mf < 4; ++mf) {
        #pragma unroll
        for (int e = 0; e < 2; ++e) {
            size_t row = (size_t)m0 + wm * 64 + mf * 16 + (lane >> 2) + e * 8;
            #pragma unroll
            for (int half = 0; half < 2; ++half) {
                int q  = 2 * (lane & 3) + half * 8;
                int bq = wn * 16 + q;
                int j  = jb + bq;
                float2 cold = *reinterpret_cast<const float2*>(c + row * 512 + j);
                float hv[2], cv[2];
                #pragma unroll
                for (int d = 0; d < 2; ++d) {
                    float gi_ = acc[mf][0 + half][e * 2 + d] + biasS[     bq + d];
                    float gf  = acc[mf][2 + half][e * 2 + d] + biasS[32 + bq + d];
                    float gg  = acc[mf][4 + half][e * 2 + d] + biasS[64 + bq + d];
                    float go  = acc[mf][6 + half][e * 2 + d] + biasS[96 + bq + d];
                    float i_ = sigm_(gi_), f_ = sigm_(gf);
                    float g_ = tanh_(gg),  o_ = sigm_(go);
                    float co = d ? cold.y : cold.x;
                    float cn = f_ * co + i_ * g_;
                    cv[d] = cn;
                    hv[d] = o_ * tanh_(cn);
                }
                *reinterpret_cast<float2*>(out + row * 512 + j) =
                    make_float2(hv[0], hv[1]);
                *reinterpret_cast<float2*>(out + HC + row * 512 + j) =
                    make_float2(cv[0], cv[1]);
            }
        }
    }
}

// ---------------- host ----------------
typedef CUresult (*EncTiledFn)(CUtensorMap*, CUtensorMapDataType, cuuint32_t,
                               void*, const cuuint64_t*, const cuuint64_t*,
                               const cuuint32_t*, const cuuint32_t*,
                               CUtensorMapInterleave, CUtensorMapSwizzle,
                               CUtensorMapL2promotion, CUtensorMapFloatOOBfill);

extern "C" void kernel_launch(void* const* d_in, const int* in_sizes, int n_in,
                              void* d_out, int out_size) {
    const float* x  = (const float*)d_in[0];
    const float* h  = (const float*)d_in[1];
    const float* c  = (const float*)d_in[2];
    const float* Wx = (const float*)d_in[3];
    const float* Wh = (const float*)d_in[4];
    const float* bx = (const float*)d_in[5];
    const float* bh = (const float*)d_in[6];
    float* out = (float*)d_out;

    static bool inited = false;
    static CUtensorMap tmA, tmB;
    if (!inited) {
        cudaFuncSetAttribute(lstm_mma,
                             cudaFuncAttributeMaxDynamicSharedMemorySize,
                             SMEM_BYTES);
        void* fn = nullptr;
        cudaDriverEntryPointQueryResult qr;
        cudaGetDriverEntryPoint("cuTensorMapEncodeTiled", &fn,
                                cudaEnableDefault, &qr);
        EncTiledFn enc = (EncTiledFn)fn;
        void *a16 = nullptr, *bt16 = nullptr;
        cudaGetSymbolAddress(&a16, g_A16);
        cudaGetSymbolAddress(&bt16, g_Bt16);
        cuuint64_t dimsA[2] = {(cuuint64_t)Ktot, (cuuint64_t)Bsz};
        cuuint64_t dimsB[2] = {(cuuint64_t)Ktot, (cuuint64_t)FH};
        cuuint64_t strides[1] = {(cuuint64_t)Ktot * 2};
        cuuint32_t box[2] = {BK, 128};
        cuuint32_t es[2] = {1, 1};
        enc(&tmA, CU_TENSOR_MAP_DATA_TYPE_UINT16, 2, a16, dimsA, strides,
            box, es, CU_TENSOR_MAP_INTERLEAVE_NONE, CU_TENSOR_MAP_SWIZZLE_128B,
            CU_TENSOR_MAP_L2_PROMOTION_L2_128B, CU_TENSOR_MAP_FLOAT_OOB_FILL_NONE);
        enc(&tmB, CU_TENSOR_MAP_DATA_TYPE_UINT16, 2, bt16, dimsB, strides,
            box, es, CU_TENSOR_MAP_INTERLEAVE_NONE, CU_TENSOR_MAP_SWIZZLE_128B,
            CU_TENSOR_MAP_L2_PROMOTION_L2_128B, CU_TENSOR_MAP_FLOAT_OOB_FILL_NONE);
        inited = true;
    }

    prep_all<<<PREP_BLKS, 256>>>(x, h, Wx, Wh);

    cudaLaunchConfig_t cfg = {};
    cfg.gridDim  = dim3(FH / BN, Bsz / BM);
    cfg.blockDim = dim3(128);
    cfg.dynamicSmemBytes = SMEM_BYTES;
    cfg.stream = 0;
    cudaLaunchAttribute attrs[1];
    attrs[0].id = cudaLaunchAttributeProgrammaticStreamSerialization;
    attrs[0].val.programmaticStreamSerializationAllowed = 1;
    cfg.attrs = attrs;
    cfg.numAttrs = 1;
    cudaLaunchKernelEx(&cfg, lstm_mma, tmA, tmB, c, bx, bh, out);
}

// round 17
// speedup vs baseline: 1.4500x; 1.4500x over previous
#include <cuda_runtime.h>
#include <cuda_fp16.h>
#include <cuda.h>
#include <cstdint>

// LSTM cell: gates = [x|h] @ [Wx;Wh] + bx + bh, fused epilogue.
// B=16384, IN=H=512, K=1024, N=4H=2048.
// Round 17: R16's TMA pipeline with ROTATING producer -- iteration it's
// TMA issue (stage it+2) is done by lane 0 of warp (it & 3), so the
// empty-wait/TMA-issue cost is spread across all 4 SMSPs instead of
// starving SMSP 0 (R16's measured failure mode). TMA path + swizzle are
// verified correct (R16 rel_err identical). prep (R13) + PDL (R15).

static constexpr int Bsz  = 16384;
static constexpr int INF  = 512;
static constexpr int Hd   = 512;
static constexpr int FH   = 2048;
static constexpr int Ktot = 1024;

#define BM 128
#define BN 128
#define BK 64
#define NSTAGE 3
#define NITER (Ktot / BK)              // 16
#define A_TILE_B 16384                 // 128 rows x 128B (SW128, no pad)
#define STG_B    32768                 // A + B
#define SMEM_BYTES (1024 + NSTAGE * STG_B)   // 99328
#define TX_BYTES 32768u

#define PREP_A_BLKS 2048
#define PREP_W_BLKS (32 * 64)
#define PREP_BLKS   (PREP_A_BLKS + PREP_W_BLKS)

__device__ __half g_A16[(size_t)Bsz * Ktot];   // 32 MB [b][k]  (x | h)
__device__ __half g_Bt16[(size_t)FH * Ktot];   // 4 MB  [n'][k] gate-interleaved(16)

// ---------------- device helpers ----------------
__device__ __forceinline__ uint32_t cvta_s(const void* p) {
    return (uint32_t)__cvta_generic_to_shared(p);
}
__device__ __forceinline__ void mbar_init(uint32_t a, uint32_t cnt) {
    asm volatile("mbarrier.init.shared.b64 [%0], %1;" :: "r"(a), "r"(cnt) : "memory");
}
__device__ __forceinline__ void mbar_arrive(uint32_t a) {
    asm volatile("mbarrier.arrive.shared.b64 _, [%0];" :: "r"(a) : "memory");
}
__device__ __forceinline__ void mbar_expect_tx(uint32_t a, uint32_t tx) {
    asm volatile("mbarrier.arrive.expect_tx.shared.b64 _, [%0], %1;"
                 :: "r"(a), "r"(tx) : "memory");
}
__device__ __forceinline__ void mbar_wait(uint32_t a, uint32_t ph) {
    uint32_t done = 0;
    while (!done) {
        asm volatile(
            "{\n\t.reg .pred p;\n\t"
            "mbarrier.try_wait.parity.acquire.cta.shared::cta.b64 p, [%1], %2, 0x989680;\n\t"
            "selp.b32 %0, 1, 0, p;\n\t}"
            : "=r"(done) : "r"(a), "r"(ph) : "memory");
    }
}
__device__ __forceinline__ void tma2d(uint32_t smem, const CUtensorMap* tm,
                                      int x, int y, uint32_t bar) {
    asm volatile(
        "cp.async.bulk.tensor.2d.shared::cta.global.tile.mbarrier::complete_tx::bytes "
        "[%0], [%1, {%2, %3}], [%4];"
        :: "r"(smem), "l"(tm), "r"(x), "r"(y), "r"(bar) : "memory");
}
__device__ __forceinline__ void ldm4(uint32_t* r, uint32_t a) {
    asm volatile("ldmatrix.sync.aligned.m8n8.x4.shared.b16 {%0,%1,%2,%3}, [%4];"
                 : "=r"(r[0]), "=r"(r[1]), "=r"(r[2]), "=r"(r[3]) : "r"(a));
}
__device__ __forceinline__ void mma16(float* d, const uint32_t* a, const uint32_t* b) {
    asm volatile(
        "mma.sync.aligned.m16n8k16.row.col.f32.f16.f16.f32 "
        "{%0,%1,%2,%3}, {%4,%5,%6,%7}, {%8,%9}, {%0,%1,%2,%3};"
        : "+f"(d[0]), "+f"(d[1]), "+f"(d[2]), "+f"(d[3])
        : "r"(a[0]), "r"(a[1]), "r"(a[2]), "r"(a[3]), "r"(b[0]), "r"(b[1]));
}
__device__ __forceinline__ float rcp_(float a) {
    float r; asm("rcp.approx.f32 %0, %1;" : "=f"(r) : "f"(a)); return r;
}
__device__ __forceinline__ float sigm_(float v) { return rcp_(1.0f + __expf(-v)); }
__device__ __forceinline__ float tanh_(float v) {
    return 2.0f * rcp_(1.0f + __expf(-2.0f * v)) - 1.0f;
}
__device__ __forceinline__ uint4 pack8h(const float4& a, const float4& b) {
    union { __half2 h2[4]; uint4 u; } u;
    u.h2[0] = __floats2half2_rn(a.x, a.y);
    u.h2[1] = __floats2half2_rn(a.z, a.w);
    u.h2[2] = __floats2half2_rn(b.x, b.y);
    u.h2[3] = __floats2half2_rn(b.z, b.w);
    return u.u;
}

// ---------------- merged prepass (R13 + PDL, validated) ----------------
__global__ void prep_all(const float* __restrict__ x, const float* __restrict__ h,
                         const float* __restrict__ Wx, const float* __restrict__ Wh)
{
    asm volatile("griddepcontrol.launch_dependents;");

    if (blockIdx.x < PREP_A_BLKS) {
        const size_t t = (size_t)blockIdx.x * 256 + threadIdx.x;
        const size_t NG = (size_t)Bsz * INF / 8;
        const size_t S  = NG / 2;
        const size_t g0 = t, g1 = t + S;
        float4 x0a = *reinterpret_cast<const float4*>(x + g0 * 8);
        float4 x0b = *reinterpret_cast<const float4*>(x + g0 * 8 + 4);
        float4 x1a = *reinterpret_cast<const float4*>(x + g1 * 8);
        float4 x1b = *reinterpret_cast<const float4*>(x + g1 * 8 + 4);
        float4 h0a = *reinterpret_cast<const float4*>(h + g0 * 8);
        float4 h0b = *reinterpret_cast<const float4*>(h + g0 * 8 + 4);
        float4 h1a = *reinterpret_cast<const float4*>(h + g1 * 8);
        float4 h1b = *reinterpret_cast<const float4*>(h + g1 * 8 + 4);
        {   size_t b = g0 >> 6, c8 = (g0 & 63) * 8;
            *reinterpret_cast<uint4*>(g_A16 + b * Ktot + c8) = pack8h(x0a, x0b);
            *reinterpret_cast<uint4*>(g_A16 + b * Ktot + 512 + c8) = pack8h(h0a, h0b);
        }
        {   size_t b = g1 >> 6, c8 = (g1 & 63) * 8;
            *reinterpret_cast<uint4*>(g_A16 + b * Ktot + c8) = pack8h(x1a, x1b);
            *reinterpret_cast<uint4*>(g_A16 + b * Ktot + 512 + c8) = pack8h(h1a, h1b);
        }
        return;
    }

    __shared__ float t[32][33];
    const int wb = blockIdx.x - PREP_A_BLKS;
    const int k0 = (wb & 31) * 32;
    const int n0 = (wb >> 5) * 32;
    const float* W = (k0 < INF) ? (Wx + (size_t)k0 * FH)
                                : (Wh + (size_t)(k0 - INF) * FH);
    const int tx = threadIdx.x & 31, ty = threadIdx.x >> 5;
    #pragma unroll
    for (int i = 0; i < 4; ++i) {
        int kk = ty + i * 8;
        t[kk][tx] = W[(size_t)kk * FH + n0 + tx];
    }
    __syncthreads();
    const int gate = n0 >> 9;
    const int j0   = n0 & 511;
    #pragma unroll
    for (int i = 0; i < 4; ++i) {
        int nn = ty + i * 8;
        int j  = j0 + nn;
        int np = ((j >> 4) << 6) + gate * 16 + (j & 15);
        g_Bt16[(size_t)np * Ktot + k0 + tx] = __float2half_rn(t[tx][nn]);
    }
}

// ---------------- main GEMM + LSTM epilogue (rotating TMA producer) -------
__global__ __launch_bounds__(128, 2)
void lstm_mma(const __grid_constant__ CUtensorMap tmA,
              const __grid_constant__ CUtensorMap tmB,
              const float* __restrict__ c,
              const float* __restrict__ bx, const float* __restrict__ bh,
              float* __restrict__ out)
{
    extern __shared__ char smraw[];
    float* biasS = reinterpret_cast<float*>(smraw);
    char*  stg0  = smraw + 1024;

    const int tid  = threadIdx.x;
    const int lane = tid & 31;
    const int wid  = tid >> 5;
    const int wm   = wid >> 1;
    const int wn   = wid & 1;
    const int m0   = blockIdx.y * BM;
    const int n0   = blockIdx.x * BN;
    const int jb   = blockIdx.x * 32;

    const uint32_t sbase = cvta_s(smraw);
    const uint32_t FULLB = sbase + 512;
    const uint32_t EMPTB = sbase + 512 + 24;
    const uint32_t STAGE0 = sbase + 1024;

    if (tid == 0) {
        #pragma unroll
        for (int s = 0; s < NSTAGE; ++s) {
            mbar_init(FULLB + s * 8, 1);      // arrive from expect_tx only
            mbar_init(EMPTB + s * 8, 128);
        }
    }
    {   int g = tid >> 5, jj = tid & 31;
        int colg = g * 512 + jb + jj;
        biasS[tid] = bx[colg] + bh[colg];
    }
    __syncthreads();    // publishes mbarrier init + bias

    // PDL: prep output must be visible before TMA reads it
    asm volatile("griddepcontrol.wait;" ::: "memory");

    // prologue: stage 0 from warp 0 lane 0, stage 1 from warp 1 lane 0
    if (tid == 0) {
        mbar_expect_tx(FULLB + 0, TX_BYTES);
        tma2d(STAGE0,            &tmA, 0,  m0, FULLB + 0);
        tma2d(STAGE0 + A_TILE_B, &tmB, 0,  n0, FULLB + 0);
    } else if (tid == 32) {
        mbar_expect_tx(FULLB + 8, TX_BYTES);
        tma2d(STAGE0 + STG_B,            &tmA, BK, m0, FULLB + 8);
        tma2d(STAGE0 + STG_B + A_TILE_B, &tmB, BK, n0, FULLB + 8);
    }

    float acc[4][8][4];
    #pragma unroll
    for (int a = 0; a < 4; ++a)
        #pragma unroll
        for (int b = 0; b < 8; ++b)
            #pragma unroll
            for (int d = 0; d < 4; ++d) acc[a][b][d] = 0.0f;

    // ldmatrix geometry with SW128 swizzle (verified in R16):
    const int grp = lane >> 3, gi = lane & 7;
    const uint32_t swm = (uint32_t)gi << 4;
    const uint32_t a_rowoff = (uint32_t)(wm * 64 + (grp & 1) * 8 + gi) * 128;
    const uint32_t b_rowoff = (uint32_t)(wn * 64 + (grp >> 1) * 8 + gi) * 128;
    const uint32_t akh = (uint32_t)((grp >> 1) * 16);
    const uint32_t bkh = (uint32_t)((grp & 1) * 16);
    uint32_t koffA[4], koffB[4];
    #pragma unroll
    for (int ks = 0; ks < 4; ++ks) {
        koffA[ks] = (akh + (uint32_t)ks * 32) ^ swm;
        koffB[ks] = (bkh + (uint32_t)ks * 32) ^ swm;
    }

    uint32_t afr[2][4][4], bfr[2][4][4];
    int fph0 = 0, fph1 = 0, fph2 = 0;
    int eph0 = 0, eph1 = 0, eph2 = 0;

    // prologue: wait stage 0, preload its ks=0 fragments
    mbar_wait(FULLB + 0, 0); fph0 = 1;
    {
        const uint32_t sA = STAGE0 + a_rowoff;
        const uint32_t sB = STAGE0 + A_TILE_B + b_rowoff;
        #pragma unroll
        for (int mf = 0; mf < 4; ++mf)
            ldm4(afr[0][mf], sA + mf * 2048 + koffA[0]);
        #pragma unroll
        for (int np = 0; np < 4; ++np)
            ldm4(bfr[0][np], sB + np * 2048 + koffB[0]);
    }

    for (int it = 0; it < NITER; ++it) {
        const int s = it % NSTAGE;

        // producer: ROTATES across warps -- lane 0 of warp (it & 3).
        // Phase bookkeeping runs in ALL threads so any future producer
        // has consistent parity state.
        if (it + 2 < NITER) {
            const int s2 = (it + 2) % NSTAGE;
            int ph = 0;
            if (it > 0) {
                ph = (s2 == 0) ? eph0 : (s2 == 1) ? eph1 : eph2;
                if (s2 == 0) eph0 ^= 1; else if (s2 == 1) eph1 ^= 1; else eph2 ^= 1;
            }
            if (tid == ((it & 3) << 5)) {
                if (it > 0) mbar_wait(EMPTB + s2 * 8, ph);
                const uint32_t dst = STAGE0 + s2 * STG_B;
                mbar_expect_tx(FULLB + s2 * 8, TX_BYTES);
                tma2d(dst,            &tmA, (it + 2) * BK, m0, FULLB + s2 * 8);
                tma2d(dst + A_TILE_B, &tmB, (it + 2) * BK, n0, FULLB + s2 * 8);
            }
        }

        const uint32_t sA = STAGE0 + s * STG_B + a_rowoff;
        const uint32_t sB = STAGE0 + s * STG_B + A_TILE_B + b_rowoff;

        #pragma unroll
        for (int ks = 0; ks < 4; ++ks) {
            const int cur = ks & 1;
            const int nxt = cur ^ 1;
            if (ks < 3) {
                #pragma unroll
                for (int mf = 0; mf < 4; ++mf)
                    ldm4(afr[nxt][mf], sA + mf * 2048 + koffA[ks + 1]);
                #pragma unroll
                for (int np = 0; np < 4; ++np)
                    ldm4(bfr[nxt][np], sB + np * 2048 + koffB[ks + 1]);
                if (ks == 2)
                    mbar_arrive(EMPTB + s * 8);   // last smem read of stage s
            } else if (it + 1 < NITER) {
                const int s1 = (it + 1) % NSTAGE;
                int ph = (s1 == 0) ? fph0 : (s1 == 1) ? fph1 : fph2;
                mbar_wait(FULLB + s1 * 8, ph);
                if (s1 == 0) fph0 ^= 1; else if (s1 == 1) fph1 ^= 1; else fph2 ^= 1;
                const uint32_t nA = STAGE0 + s1 * STG_B + a_rowoff;
                const uint32_t nB = STAGE0 + s1 * STG_B + A_TILE_B + b_rowoff;
                #pragma unroll
                for (int mf = 0; mf < 4; ++mf)
                    ldm4(afr[nxt][mf], nA + mf * 2048 + koffA[0]);
                #pragma unroll
                for (int np = 0; np < 4; ++np)
                    ldm4(bfr[nxt][np], nB + np * 2048 + koffB[0]);
            }
            #pragma unroll
            for (int mf = 0; mf < 4; ++mf)
                #pragma unroll
                for (int np = 0; np < 4; ++np) {
                    mma16(acc[mf][np * 2 + 0], afr[cur][mf], &bfr[cur][np][0]);
                    mma16(acc[mf][np * 2 + 1], afr[cur][mf], &bfr[cur][np][2]);
                }
        }
    }

    // ---- fused LSTM epilogue (thread-local: all 4 gates per j) ----
    const size_t HC = (size_t)Bsz * Hd;
    #pragma unroll
    for (int mf = 0; mf < 4; ++mf) {
        #pragma unroll
        for (int e = 0; e < 2; ++e) {
            size_t row = (size_t)m0 + wm * 64 + mf * 16 + (lane >> 2) + e * 8;
            #pragma unroll
            for (int half = 0; half < 2; ++half) {
                int q  = 2 * (lane & 3) + half * 8;
                int bq = wn * 16 + q;
                int j  = jb + bq;
                float2 cold = *reinterpret_cast<const float2*>(c + row * 512 + j);
                float hv[2], cv[2];
                #pragma unroll
                for (int d = 0; d < 2; ++d) {
                    float gi_ = acc[mf][0 + half][e * 2 + d] + biasS[     bq + d];
                    float gf  = acc[mf][2 + half][e * 2 + d] + biasS[32 + bq + d];
                    float gg  = acc[mf][4 + half][e * 2 + d] + biasS[64 + bq + d];
                    float go  = acc[mf][6 + half][e * 2 + d] + biasS[96 + bq + d];
                    float i_ = sigm_(gi_), f_ = sigm_(gf);
                    float g_ = tanh_(gg),  o_ = sigm_(go);
                    float co = d ? cold.y : cold.x;
                    float cn = f_ * co + i_ * g_;
                    cv[d] = cn;
                    hv[d] = o_ * tanh_(cn);
                }
                *reinterpret_cast<float2*>(out + row * 512 + j) =
                    make_float2(hv[0], hv[1]);
                *reinterpret_cast<float2*>(out + HC + row * 512 + j) =
                    make_float2(cv[0], cv[1]);
            }
        }
    }
}

// ---------------- host ----------------
typedef CUresult (*EncTiledFn)(CUtensorMap*, CUtensorMapDataType, cuuint32_t,
                               void*, const cuuint64_t*, const cuuint64_t*,
                               const cuuint32_t*, const cuuint32_t*,
                               CUtensorMapInterleave, CUtensorMapSwizzle,
                               CUtensorMapL2promotion, CUtensorMapFloatOOBfill);

extern "C" void kernel_launch(void* const* d_in, const int* in_sizes, int n_in,
                              void* d_out, int out_size) {
    const float* x  = (const float*)d_in[0];
    const float* h  = (const float*)d_in[1];
    const float* c  = (const float*)d_in[2];
    const float* Wx = (const float*)d_in[3];
    const float* Wh = (const float*)d_in[4];
    const float* bx = (const float*)d_in[5];
    const float* bh = (const float*)d_in[6];
    float* out = (float*)d_out;

    static bool inited = false;
    static CUtensorMap tmA, tmB;
    if (!inited) {
        cudaFuncSetAttribute(lstm_mma,
                             cudaFuncAttributeMaxDynamicSharedMemorySize,
                             SMEM_BYTES);
        void* fn = nullptr;
        cudaDriverEntryPointQueryResult qr;
        cudaGetDriverEntryPoint("cuTensorMapEncodeTiled", &fn,
                                cudaEnableDefault, &qr);
        EncTiledFn enc = (EncTiledFn)fn;
        void *a16 = nullptr, *bt16 = nullptr;
        cudaGetSymbolAddress(&a16, g_A16);
        cudaGetSymbolAddress(&bt16, g_Bt16);
        cuuint64_t dimsA[2] = {(cuuint64_t)Ktot, (cuuint64_t)Bsz};
        cuuint64_t dimsB[2] = {(cuuint64_t)Ktot, (cuuint64_t)FH};
        cuuint64_t strides[1] = {(cuuint64_t)Ktot * 2};
        cuuint32_t box[2] = {BK, 128};
        cuuint32_t es[2] = {1, 1};
        enc(&tmA, CU_TENSOR_MAP_DATA_TYPE_UINT16, 2, a16, dimsA, strides,
            box, es, CU_TENSOR_MAP_INTERLEAVE_NONE, CU_TENSOR_MAP_SWIZZLE_128B,
            CU_TENSOR_MAP_L2_PROMOTION_L2_128B, CU_TENSOR_MAP_FLOAT_OOB_FILL_NONE);
        enc(&tmB, CU_TENSOR_MAP_DATA_TYPE_UINT16, 2, bt16, dimsB, strides,
            box, es, CU_TENSOR_MAP_INTERLEAVE_NONE, CU_TENSOR_MAP_SWIZZLE_128B,
            CU_TENSOR_MAP_L2_PROMOTION_L2_128B, CU_TENSOR_MAP_FLOAT_OOB_FILL_NONE);
        inited = true;
    }

    prep_all<<<PREP_BLKS, 256>>>(x, h, Wx, Wh);

    cudaLaunchConfig_t cfg = {};
    cfg.gridDim  = dim3(FH / BN, Bsz / BM);
    cfg.blockDim = dim3(128);
    cfg.dynamicSmemBytes = SMEM_BYTES;
    cfg.stream = 0;
    cudaLaunchAttribute attrs[1];
    attrs[0].id = cudaLaunchAttributeProgrammaticStreamSerialization;
    attrs[0].val.programmaticStreamSerializationAllowed = 1;
    cfg.attrs = attrs;
    cfg.numAttrs = 1;
    cudaLaunchKernelEx(&cfg, lstm_mma, tmA, tmB, c, bx, bh, out);
}